// round 5
// baseline (speedup 1.0000x reference)
#include <cuda_runtime.h>
#include <math.h>

#define B_   32
#define C_   128
#define HW_  256
#define V_   8192
#define TOT  (B_*C_*HW_)   // 1048576

// ---------------- scratch (no allocations allowed) ----------------
__device__ float               g_frest[TOT];
__device__ float               g_restNC[V_*C_];     // up to 8192 rows x 128
__device__ float               g_hup[TOT];
__device__ unsigned long long  g_keys[V_];
__device__ float               g_esq[V_];
__device__ float               g_W[240];            // W1@0(16), W2@16(32), W4@48(64), W8@112(128)
__device__ float               g_lossPart[5*256];

// Keys cubic (a = -0.5), matches jax.image _keys_cubic_kernel
__device__ __forceinline__ double keys_cubic(double x){
    if (x >= 2.0) return 0.0;
    if (x >= 1.0) return ((-0.5*x + 2.5)*x - 4.0)*x + 2.0;
    return ((1.5*x - 2.5)*x)*x + 1.0;
}

// ---------------- init: f_hat=0, f_rest=f, bicubic weight mats ----------------
__global__ void k_init(const float* __restrict__ f, float* __restrict__ out){
    int i = blockIdx.x*blockDim.x + threadIdx.x;
    int stride = gridDim.x*blockDim.x;
    for (; i < TOT; i += stride){ out[i] = 0.f; g_frest[i] = f[i]; }
    if (blockIdx.x == 0 && threadIdx.x == 0){
        for (int o=0;o<16;o++) g_W[o] = 1.f;                 // pn=1: renormalized single tap = 1
        const int offs[3] = {16,48,112};
        const int pns[3]  = {2,4,8};
        for (int t=0;t<3;t++){
            int pn = pns[t]; int off = offs[t];
            double inv_scale = (double)pn / 16.0;            // scale = 16/pn (upsample)
            for (int o=0;o<16;o++){
                double sf = ((double)o + 0.5) * inv_scale - 0.5;   // half-pixel centers
                double wv[8]; double wsum = 0.0;
                for (int ii=0; ii<pn; ii++){
                    double k = keys_cubic(fabs(sf - (double)ii));
                    wv[ii] = k; wsum += k;
                }
                for (int ii=0; ii<pn; ii++)
                    g_W[off + o*pn + ii] = (float)(wv[ii]/wsum);   // column renormalization
            }
        }
    }
}

// ---------------- ||e||^2 ----------------
__global__ void k_esq(const float* __restrict__ E){
    __shared__ float r[128];
    int v = blockIdx.x, c = threadIdx.x;
    float x = E[v*C_ + c];
    r[c] = x*x;
    __syncthreads();
    for (int s=64; s>0; s>>=1){
        if (c < s) r[c] += r[c+s];
        __syncthreads();
    }
    if (c==0) g_esq[v] = r[0];
}

__global__ void k_keyinit(int N){
    int i = blockIdx.x*256 + threadIdx.x;
    if (i < N) g_keys[i] = ~0ull;
}

// ---------------- area pool f_rest -> rest_NC [N][C] ----------------
__global__ void k_pool(int pn){
    __shared__ float s[256];
    int bc = blockIdx.x;           // b*128 + c
    int b = bc >> 7, c = bc & 127;
    int tid = threadIdx.x;
    s[tid] = g_frest[bc*256 + tid];
    __syncthreads();
    int S = 16/pn;
    if (tid < pn*pn){
        int i = tid / pn, j = tid - i*pn;
        float sum = 0.f;
        for (int dh=0; dh<S; dh++)
            for (int dw=0; dw<S; dw++)
                sum += s[(i*S+dh)*16 + j*S + dw];
        g_restNC[(b*pn*pn + tid)*C_ + c] = sum * (1.f/(float)(S*S));
    }
}

// ---------------- argmin over codebook: 128x128 tiles, 8x8 per thread ----------------
// score = e_sq[v] - 2*dot(r,e)  (row-constant ||r||^2 dropped; same argmin)
// key = sortable(score)<<32 | v  -> atomicMin == (min score, lowest v on ties)
__global__ __launch_bounds__(256) void k_argmin(const float* __restrict__ E, int N, int vchunk){
    __shared__ __align__(16) float sA[16][128];
    __shared__ __align__(16) float sB[16][128];
    __shared__ unsigned long long sMin[128];
    int tid = threadIdx.x;
    int tx = tid & 15, ty = tid >> 4;
    int n0 = blockIdx.x * 128;
    int v0base = blockIdx.y * vchunk;

    unsigned long long best[8];
#pragma unroll
    for (int i=0;i<8;i++) best[i] = ~0ull;

    int lrow = tid >> 1;
    int lkof = (tid & 1) << 3;
    bool avalid = (n0 + lrow) < N;
    const float* aptr = g_restNC + (size_t)(n0+lrow)*C_ + lkof;

    for (int v0 = v0base; v0 < v0base + vchunk; v0 += 128){
        float acc[8][8];
#pragma unroll
        for (int i=0;i<8;i++)
#pragma unroll
            for (int j=0;j<8;j++) acc[i][j]=0.f;

        const float* bptr = E + (size_t)(v0+lrow)*C_ + lkof;
        for (int k0=0;k0<128;k0+=16){
            float4 a0,a1;
            if (avalid){ a0 = *(const float4*)(aptr + k0); a1 = *(const float4*)(aptr + k0 + 4); }
            else       { a0 = make_float4(0,0,0,0); a1 = a0; }
            float4 b0 = *(const float4*)(bptr + k0);
            float4 b1 = *(const float4*)(bptr + k0 + 4);
            sA[lkof+0][lrow]=a0.x; sA[lkof+1][lrow]=a0.y; sA[lkof+2][lrow]=a0.z; sA[lkof+3][lrow]=a0.w;
            sA[lkof+4][lrow]=a1.x; sA[lkof+5][lrow]=a1.y; sA[lkof+6][lrow]=a1.z; sA[lkof+7][lrow]=a1.w;
            sB[lkof+0][lrow]=b0.x; sB[lkof+1][lrow]=b0.y; sB[lkof+2][lrow]=b0.z; sB[lkof+3][lrow]=b0.w;
            sB[lkof+4][lrow]=b1.x; sB[lkof+5][lrow]=b1.y; sB[lkof+6][lrow]=b1.z; sB[lkof+7][lrow]=b1.w;
            __syncthreads();
#pragma unroll
            for (int kk=0;kk<16;kk++){
                float4 av0 = *(const float4*)&sA[kk][ty*8];
                float4 av1 = *(const float4*)&sA[kk][ty*8+4];
                float4 bv0 = *(const float4*)&sB[kk][tx*8];
                float4 bv1 = *(const float4*)&sB[kk][tx*8+4];
                float a[8] = {av0.x,av0.y,av0.z,av0.w,av1.x,av1.y,av1.z,av1.w};
                float b[8] = {bv0.x,bv0.y,bv0.z,bv0.w,bv1.x,bv1.y,bv1.z,bv1.w};
#pragma unroll
                for (int i=0;i<8;i++)
#pragma unroll
                    for (int j=0;j<8;j++) acc[i][j] = fmaf(a[i], b[j], acc[i][j]);
            }
            __syncthreads();
        }
#pragma unroll
        for (int j=0;j<8;j++){
            int v = v0 + tx*8 + j;
            float eq = g_esq[v];
#pragma unroll
            for (int i=0;i<8;i++){
                float s = fmaf(-2.f, acc[i][j], eq);
                unsigned u = __float_as_uint(s);
                u = (u & 0x80000000u) ? ~u : (u | 0x80000000u);
                unsigned long long key = ((unsigned long long)u << 32) | (unsigned long long)(unsigned)v;
                if (key < best[i]) best[i] = key;
            }
        }
    }
    if (tid < 128) sMin[tid] = ~0ull;
    __syncthreads();
#pragma unroll
    for (int i=0;i<8;i++) atomicMin(&sMin[ty*8+i], best[i]);
    __syncthreads();
    if (tid < 128 && n0 + tid < N) atomicMin(&g_keys[n0+tid], sMin[tid]);
}

// ---------------- gather codes + bicubic upsample to 16x16 ----------------
__global__ void k_gather(const float* __restrict__ E, int pn, int woff){
    int bp = blockIdx.x; int b = bp >> 8; int pix = bp & 255;
    int c = threadIdx.x;   // 128
    float acc;
    if (pn == 16){
        int v = (int)(unsigned)(g_keys[b*256 + pix]);
        acc = E[(size_t)v*C_ + c];
    } else {
        int o1 = pix >> 4, o2 = pix & 15;
        acc = 0.f;
        for (int i1=0;i1<pn;i1++){
            float w1 = g_W[woff + o1*pn + i1];
            if (w1 == 0.f) continue;
            for (int i2=0;i2<pn;i2++){
                float w2 = g_W[woff + o2*pn + i2];
                if (w2 == 0.f) continue;
                int v = (int)(unsigned)(g_keys[(b*pn + i1)*pn + i2]);
                acc = fmaf(w1*w2, E[(size_t)v*C_ + c], acc);
            }
        }
    }
    g_hup[(b*C_ + c)*HW_ + pix] = acc;
}

// ---------------- conv3x3 + Phi mix + f_hat/f_rest update + loss partial ----------------
__global__ __launch_bounds__(256) void k_conv(
    const float* __restrict__ phiw, const float* __restrict__ phib,
    const float* __restrict__ f, float* __restrict__ fhat,
    int kphi, int si)
{
    __shared__ __align__(16) float sIn[16][256];
    __shared__ __align__(16) float sW[16][16][12];
    __shared__ float sRed[256];
    int b = blockIdx.x, ocg = blockIdx.y;
    int tid = threadIdx.x;
    int ocl = tid >> 4, h = tid & 15;
    int oc = ocg*16 + ocl;

    float acc[16];
#pragma unroll
    for (int x=0;x<16;x++) acc[x]=0.f;

    const float* inb = g_hup + (size_t)b*C_*HW_;
    for (int icc=0; icc<128; icc+=16){
#pragma unroll
        for (int t=0;t<16;t++)
            sIn[t][tid] = inb[(icc+t)*HW_ + tid];
        {
            const float* wp = phiw + (((size_t)kphi*C_ + oc)*C_ + (icc + h))*9;
#pragma unroll
            for (int k=0;k<9;k++) sW[h][ocl][k] = wp[k];
        }
        __syncthreads();
        for (int ic=0; ic<16; ic++){
            float4 wa = *(const float4*)&sW[ic][ocl][0];
            float4 wb = *(const float4*)&sW[ic][ocl][4];
            float w8 = sW[ic][ocl][8];
            float w[9] = {wa.x,wa.y,wa.z,wa.w,wb.x,wb.y,wb.z,wb.w,w8};
            float rr[3][18];
#pragma unroll
            for (int dh=0; dh<3; dh++){
                int hh = h + dh - 1;
                rr[dh][0] = 0.f; rr[dh][17] = 0.f;
                if (hh >= 0 && hh < 16){
                    const float4* rp = (const float4*)&sIn[ic][hh*16];
                    float4 v0 = rp[0], v1 = rp[1], v2 = rp[2], v3 = rp[3];
                    rr[dh][1]=v0.x; rr[dh][2]=v0.y; rr[dh][3]=v0.z; rr[dh][4]=v0.w;
                    rr[dh][5]=v1.x; rr[dh][6]=v1.y; rr[dh][7]=v1.z; rr[dh][8]=v1.w;
                    rr[dh][9]=v2.x; rr[dh][10]=v2.y; rr[dh][11]=v2.z; rr[dh][12]=v2.w;
                    rr[dh][13]=v3.x; rr[dh][14]=v3.y; rr[dh][15]=v3.z; rr[dh][16]=v3.w;
                } else {
#pragma unroll
                    for (int x=0;x<16;x++) rr[dh][1+x]=0.f;
                }
            }
#pragma unroll
            for (int x=0;x<16;x++){
                float s = 0.f;
#pragma unroll
                for (int dh=0;dh<3;dh++)
#pragma unroll
                    for (int dw=0;dw<3;dw++)
                        s = fmaf(rr[dh][x+dw], w[dh*3+dw], s);
                acc[x] += s;
            }
        }
        __syncthreads();
    }

    float bias = phib[kphi*C_ + oc];
    int base = (b*C_ + oc)*HW_ + h*16;
    float lsum = 0.f;
#pragma unroll
    for (int x=0;x<16;x++){
        float y  = acc[x] + bias;
        float hi = g_hup[base + x];
        float hp = 0.5f*hi + 0.5f*y;          // Phi: x*(1-r) + conv(x)*r, r=0.5
        float fh = fhat[base + x] + hp;
        fhat[base + x] = fh;
        g_frest[base + x] -= hp;
        float d = fh - f[base + x];
        lsum = fmaf(d, d, lsum);
    }
    sRed[tid] = lsum;
    __syncthreads();
    for (int s=128; s>0; s>>=1){
        if (tid < s) sRed[tid] += sRed[tid+s];
        __syncthreads();
    }
    if (tid == 0) g_lossPart[si*256 + ocg*32 + b] = sRed[0];
}

// ---------------- loss finalize (deterministic, double) ----------------
__global__ void k_final(float* out){
    if (threadIdx.x == 0){
        double total = 0.0;
        for (int s=0;s<5;s++){
            double m = 0.0;
            for (int i=0;i<256;i++) m += (double)g_lossPart[s*256+i];
            total += 1.25 * (m / (double)TOT);   // (1+BETA)*mean
        }
        out[TOT] = (float)(total / 5.0);          // / SN
    }
}

// ---------------- launch ----------------
extern "C" void kernel_launch(void* const* d_in, const int* in_sizes, int n_in,
                              void* d_out, int out_size){
    (void)in_sizes; (void)n_in; (void)out_size;
    const float* f  = (const float*)d_in[0];
    const float* E  = (const float*)d_in[1];
    const float* pw = (const float*)d_in[2];
    const float* pb = (const float*)d_in[3];
    float* out = (float*)d_out;

    // replicate np.linspace(1/12, 11/12, 4) + argmin tick selection in double
    double start = 1.0/12.0, stop = 1.0 - 1.0/12.0;
    double step = (stop - start) / 3.0;
    double ticks[4];
    for (int i=0;i<4;i++) ticks[i] = (double)i*step + start;
    ticks[3] = stop;
    int kphi[5];
    for (int si=0;si<5;si++){
        double t = (double)si / 4.0;
        int best = 0;
        for (int k=1;k<4;k++)
            if (fabs(ticks[k]-t) < fabs(ticks[best]-t)) best = k;
        kphi[si] = best;
    }

    k_init<<<512, 256>>>(f, out);
    k_esq<<<V_, 128>>>(E);

    const int pns[5]  = {1,2,4,8,16};
    const int woff[5] = {0,16,48,112,0};
    for (int si=0;si<5;si++){
        int pn = pns[si];
        int N  = B_*pn*pn;
        k_keyinit<<<(N+255)/256, 256>>>(N);
        k_pool<<<B_*C_, 256>>>(pn);
        int nblk = (N + 127)/128;
        int vsplit = 1;
        while (nblk*vsplit < 148 && vsplit < 64) vsplit <<= 1;
        dim3 ga(nblk, vsplit);
        k_argmin<<<ga, 256>>>(E, N, V_/vsplit);
        k_gather<<<B_*HW_, 128>>>(E, pn, woff[si]);
        dim3 gc(B_, 8);
        k_conv<<<gc, 256>>>(pw, pb, f, out, kphi[si], si);
    }
    k_final<<<1, 32>>>(out);
}